// round 1
// baseline (speedup 1.0000x reference)
#include <cuda_runtime.h>
#include <math.h>

// Problem constants (fixed by the dataset)
#define B_ROWS 65536
#define T_DIM  365

// ---------------------------------------------------------------------------
// Scratch (device globals: allocation-free per harness rules)
// ---------------------------------------------------------------------------
__device__ float g_h1  [(size_t)B_ROWS * 512];   // relu(x@W1+b1)
__device__ float g_h2  [(size_t)B_ROWS * 256];   // relu(h1@W2+b2)
__device__ float g_comb[(size_t)B_ROWS * 160];   // [h3 | stat_features]
__device__ float g_c1  [(size_t)B_ROWS * 64];    // relu(comb@Wc1+bc1)
__device__ float g_c2  [(size_t)B_ROWS * 32];    // relu(c1@Wc2+bc2)

// ---------------------------------------------------------------------------
// Generic tiled fp32 GEMM:  C[:, :N] = relu(A[M,K] @ W[K,N] + bias)
// A row-major (lda = K), W row-major (ldw = N), C row-major with stride ldc.
// MT x NT tile per CTA, KC k-chunk, TM x TN microtile per thread.
// ---------------------------------------------------------------------------
template<int MT, int NT, int KC, int TM, int TN>
__global__ void __launch_bounds__((MT/TM)*(NT/TN))
gemm_bias_relu(const float* __restrict__ A, const float* __restrict__ W,
               const float* __restrict__ bias, float* __restrict__ C,
               int M, int N, int K, int ldc)
{
    constexpr int THREADS = (MT/TM)*(NT/TN);
    constexpr int AP = MT + 4;                 // pad: keeps float4 alignment + kills store conflicts
    __shared__ float As[KC][AP];               // A chunk, transposed: As[k][m]
    __shared__ float Bs[KC][NT];               // W chunk: Bs[k][n]

    const int tid    = threadIdx.x;
    const int ntiles = NT / TN;
    const int tn_idx = tid % ntiles;
    const int tm_idx = tid / ntiles;
    const int m0  = blockIdx.y * MT;
    const int n0  = blockIdx.x * NT;
    const int tm0 = tm_idx * TM;
    const int tn0 = tn_idx * TN;

    float acc[TM][TN];
    #pragma unroll
    for (int i = 0; i < TM; i++)
        #pragma unroll
        for (int j = 0; j < TN; j++) acc[i][j] = 0.0f;

    constexpr int EA = MT * KC / THREADS;      // A elements per thread per chunk
    constexpr int EB = NT * KC / THREADS;      // W elements per thread per chunk

    for (int k0 = 0; k0 < K; k0 += KC) {
        // --- stage A chunk (global -> smem, transposed) ---
        #pragma unroll
        for (int e = 0; e < EA; e++) {
            int flat = tid + e * THREADS;
            int m = flat / KC;
            int k = flat % KC;
            int gk = k0 + k;
            float v = (gk < K) ? A[(size_t)(m0 + m) * K + gk] : 0.0f;
            As[k][m] = v;
        }
        // --- stage W chunk ---
        #pragma unroll
        for (int e = 0; e < EB; e++) {
            int flat = tid + e * THREADS;
            int k = flat / NT;
            int n = flat % NT;
            int gk = k0 + k;
            float v = (gk < K) ? W[(size_t)gk * N + n0 + n] : 0.0f;
            Bs[k][n] = v;
        }
        __syncthreads();

        // --- compute ---
        #pragma unroll
        for (int k = 0; k < KC; k++) {
            float a[TM], b[TN];
            #pragma unroll
            for (int i = 0; i < TM; i += 4) {
                float4 t = *(const float4*)&As[k][tm0 + i];
                a[i] = t.x; a[i+1] = t.y; a[i+2] = t.z; a[i+3] = t.w;
            }
            if (TN % 4 == 0) {
                #pragma unroll
                for (int j = 0; j < TN; j += 4) {
                    float4 t = *(const float4*)&Bs[k][tn0 + j];
                    b[j] = t.x; b[j+1] = t.y; b[j+2] = t.z; b[j+3] = t.w;
                }
            } else {
                #pragma unroll
                for (int j = 0; j < TN; j++) b[j] = Bs[k][tn0 + j];
            }
            #pragma unroll
            for (int i = 0; i < TM; i++)
                #pragma unroll
                for (int j = 0; j < TN; j++)
                    acc[i][j] = fmaf(a[i], b[j], acc[i][j]);
        }
        __syncthreads();
    }

    // --- epilogue: bias + relu ---
    #pragma unroll
    for (int i = 0; i < TM; i++) {
        #pragma unroll
        for (int j = 0; j < TN; j++) {
            float v = acc[i][j] + bias[n0 + tn0 + j];
            v = fmaxf(v, 0.0f);
            C[(size_t)(m0 + tm0 + i) * ldc + n0 + tn0 + j] = v;
        }
    }
}

// ---------------------------------------------------------------------------
// Per-row statistics + 6->32 projection. One warp per row; single global pass
// (row values kept in registers), warp-shuffle reductions.
// Writes stat_features into g_comb[:, 128:160].
// ---------------------------------------------------------------------------
__global__ void stats_kernel(const float* __restrict__ x,
                             const float* __restrict__ Ws,
                             const float* __restrict__ bs,
                             float* __restrict__ comb)
{
    int gwarp = (blockIdx.x * blockDim.x + threadIdx.x) >> 5;
    int lane  = threadIdx.x & 31;
    if (gwarp >= B_ROWS) return;

    const float* row = x + (size_t)gwarp * T_DIM;
    constexpr int NV = (T_DIM + 31) / 32;      // 12
    float v[NV];
    float sum = 0.0f, mn = INFINITY, mx = -INFINITY;
    #pragma unroll
    for (int i = 0; i < NV; i++) {
        int k = lane + 32 * i;
        float t = (k < T_DIM) ? row[k] : 0.0f;
        v[i] = t;
        if (k < T_DIM) { sum += t; mn = fminf(mn, t); mx = fmaxf(mx, t); }
    }
    #pragma unroll
    for (int off = 16; off; off >>= 1) {
        sum += __shfl_xor_sync(0xffffffffu, sum, off);
        mn   = fminf(mn, __shfl_xor_sync(0xffffffffu, mn, off));
        mx   = fmaxf(mx, __shfl_xor_sync(0xffffffffu, mx, off));
    }
    float mean = sum / (float)T_DIM;

    float s2 = 0.0f, s3 = 0.0f, s4 = 0.0f;
    #pragma unroll
    for (int i = 0; i < NV; i++) {
        int k = lane + 32 * i;
        if (k < T_DIM) {
            float c  = v[i] - mean;
            float c2 = c * c;
            s2 += c2; s3 += c2 * c; s4 += c2 * c2;
        }
    }
    #pragma unroll
    for (int off = 16; off; off >>= 1) {
        s2 += __shfl_xor_sync(0xffffffffu, s2, off);
        s3 += __shfl_xor_sync(0xffffffffu, s3, off);
        s4 += __shfl_xor_sync(0xffffffffu, s4, off);
    }
    float var  = s2 / (float)(T_DIM - 1);      // unbiased
    float sd   = sqrtf(var);
    float skew = (s3 / (float)T_DIM) / (sd * sd * sd + 1e-8f);
    float kurt = (s4 / (float)T_DIM) / (var * var + 1e-8f);   // std^4 == var^2

    float st[6] = { mean, sd, mn, mx, skew, kurt };
    // stat_features[j] = bs[j] + sum_i st[i] * Ws[i][j];  lane == j (32 outputs)
    float o = bs[lane];
    #pragma unroll
    for (int i = 0; i < 6; i++) o = fmaf(st[i], Ws[i * 32 + lane], o);
    comb[(size_t)gwarp * 160 + 128 + lane] = o;
}

// ---------------------------------------------------------------------------
// Final head: out = sigmoid(c2 @ Wc3 + bc3) * 4 + 6. One warp per row.
// ---------------------------------------------------------------------------
__global__ void head_final(const float* __restrict__ c2,
                           const float* __restrict__ Wc3,
                           const float* __restrict__ bc3,
                           float* __restrict__ out)
{
    int gwarp = (blockIdx.x * blockDim.x + threadIdx.x) >> 5;
    int lane  = threadIdx.x & 31;
    if (gwarp >= B_ROWS) return;
    float v = c2[(size_t)gwarp * 32 + lane] * Wc3[lane];
    #pragma unroll
    for (int off = 16; off; off >>= 1) v += __shfl_xor_sync(0xffffffffu, v, off);
    if (lane == 0) {
        float z = v + bc3[0];
        out[gwarp] = 4.0f / (1.0f + expf(-z)) + 6.0f;
    }
}

// ---------------------------------------------------------------------------
// Launch
// ---------------------------------------------------------------------------
extern "C" void kernel_launch(void* const* d_in, const int* in_sizes, int n_in,
                              void* d_out, int out_size)
{
    const float* x   = (const float*)d_in[0];
    const float* W1  = (const float*)d_in[1];
    const float* b1  = (const float*)d_in[2];
    const float* W2  = (const float*)d_in[3];
    const float* b2  = (const float*)d_in[4];
    const float* W3  = (const float*)d_in[5];
    const float* b3  = (const float*)d_in[6];
    const float* Ws  = (const float*)d_in[7];
    const float* bs  = (const float*)d_in[8];
    const float* Wc1 = (const float*)d_in[9];
    const float* bc1 = (const float*)d_in[10];
    const float* Wc2 = (const float*)d_in[11];
    const float* bc2 = (const float*)d_in[12];
    const float* Wc3 = (const float*)d_in[13];
    const float* bc3 = (const float*)d_in[14];
    float* out = (float*)d_out;

    float *h1, *h2, *comb, *c1, *c2;
    cudaGetSymbolAddress((void**)&h1,   g_h1);
    cudaGetSymbolAddress((void**)&h2,   g_h2);
    cudaGetSymbolAddress((void**)&comb, g_comb);
    cudaGetSymbolAddress((void**)&c1,   g_c1);
    cudaGetSymbolAddress((void**)&c2,   g_c2);

    // Stats (independent of GEMM chain; must precede gemm4)
    stats_kernel<<<B_ROWS / 8, 256>>>(x, Ws, bs, comb);

    // h1 = relu(x @ W1 + b1)           [65536,365]x[365,512]
    gemm_bias_relu<128,128,16,8,8><<<dim3(512/128, B_ROWS/128), 256>>>(
        x, W1, b1, h1, B_ROWS, 512, T_DIM, 512);
    // h2 = relu(h1 @ W2 + b2)          [65536,512]x[512,256]
    gemm_bias_relu<128,128,16,8,8><<<dim3(256/128, B_ROWS/128), 256>>>(
        h1, W2, b2, h2, B_ROWS, 256, 512, 256);
    // h3 = relu(h2 @ W3 + b3) -> comb[:, 0:128]    [65536,256]x[256,128]
    gemm_bias_relu<128,128,16,8,8><<<dim3(1, B_ROWS/128), 256>>>(
        h2, W3, b3, comb, B_ROWS, 128, 256, 160);
    // c1 = relu(comb @ Wc1 + bc1)      [65536,160]x[160,64]
    gemm_bias_relu<128,64,16,8,4><<<dim3(1, B_ROWS/128), 256>>>(
        comb, Wc1, bc1, c1, B_ROWS, 64, 160, 64);
    // c2 = relu(c1 @ Wc2 + bc2)        [65536,64]x[64,32]
    gemm_bias_relu<128,32,16,8,2><<<dim3(1, B_ROWS/128), 256>>>(
        c1, Wc2, bc2, c2, B_ROWS, 32, 64, 32);
    // out = sigmoid(c2 @ Wc3 + bc3)*4+6
    head_final<<<B_ROWS / 8, 256>>>(c2, Wc3, bc3, out);
}

// round 3
// speedup vs baseline: 2.4551x; 2.4551x over previous
#include <cuda_runtime.h>
#include <cuda_bf16.h>
#include <math.h>
#include <stdint.h>

#define B_ROWS 65536
#define T_DIM  365

typedef __nv_bfloat16 bf16;

// ---------------------------------------------------------------------------
// Scratch (device globals)
// ---------------------------------------------------------------------------
__device__ bf16 g_xhi [(size_t)B_ROWS * 384];
__device__ bf16 g_xlo [(size_t)B_ROWS * 384];
__device__ bf16 g_h1hi[(size_t)B_ROWS * 512];
__device__ bf16 g_h1lo[(size_t)B_ROWS * 512];
__device__ bf16 g_h2hi[(size_t)B_ROWS * 256];
__device__ bf16 g_h2lo[(size_t)B_ROWS * 256];
__device__ bf16 g_cbhi[(size_t)B_ROWS * 192];   // [h3(128) | stats(32) | zero(32)]
__device__ bf16 g_cblo[(size_t)B_ROWS * 192];
__device__ bf16 g_c1hi[(size_t)B_ROWS * 64];
__device__ bf16 g_c1lo[(size_t)B_ROWS * 64];
__device__ float g_c2 [(size_t)B_ROWS * 32];
// weights transposed to [N, Kpad] bf16 hi/lo
__device__ bf16 g_w1hi[512*384], g_w1lo[512*384];
__device__ bf16 g_w2hi[256*512], g_w2lo[256*512];
__device__ bf16 g_w3hi[128*256], g_w3lo[128*256];
__device__ bf16 g_w4hi[64*192],  g_w4lo[64*192];
__device__ bf16 g_w5hi[32*64],   g_w5lo[32*64];

// ---------------------------------------------------------------------------
// Baseline-PTX helpers (all sm_80+; assemble on plain sm_103)
// ---------------------------------------------------------------------------
__device__ __forceinline__ uint32_t smem_u32(const void* p) {
    uint32_t a;
    asm("{ .reg .u64 t; cvta.to.shared.u64 t, %1; cvt.u32.u64 %0, t; }" : "=r"(a) : "l"(p));
    return a;
}
__device__ __forceinline__ void cpa16(uint32_t dst, const void* src) {
    asm volatile("cp.async.cg.shared.global [%0], [%1], 16;" :: "r"(dst), "l"(src));
}
#define CP_COMMIT() asm volatile("cp.async.commit_group;" ::: "memory")
template<int N>
__device__ __forceinline__ void cp_wait() {
    asm volatile("cp.async.wait_group %0;" :: "n"(N) : "memory");
}
#define LDM4(r, addr) \
    asm volatile("ldmatrix.sync.aligned.m8n8.x4.shared.b16 {%0,%1,%2,%3}, [%4];" \
        : "=r"((r)[0]), "=r"((r)[1]), "=r"((r)[2]), "=r"((r)[3]) : "r"(addr))
#define MMA_BF16(d, a, b) \
    asm volatile("mma.sync.aligned.m16n8k16.row.col.f32.bf16.bf16.f32 " \
        "{%0,%1,%2,%3}, {%4,%5,%6,%7}, {%8,%9}, {%0,%1,%2,%3};" \
        : "+f"((d)[0]), "+f"((d)[1]), "+f"((d)[2]), "+f"((d)[3]) \
        : "r"((a)[0]), "r"((a)[1]), "r"((a)[2]), "r"((a)[3]), \
          "r"((b)[0]), "r"((b)[1]))

// ---------------------------------------------------------------------------
// mma.sync GEMM: out[128 x NT] = relu(A @ W^T + bias)
// A: [B, KPAD] bf16 hi/lo; W: [N, KPAD] bf16 hi/lo (pre-transposed).
// 3-pass split: D = Ahi*Bhi + Alo*Bhi + Ahi*Blo (fp32 reg accum).
// smem rows: 128B = [hi 4x16B granules | lo 4x16B], XOR-swizzled, k-chunk 32.
// 2-stage cp.async pipeline.
// ---------------------------------------------------------------------------
template<int NT, int NC, bool SPLIT_OUT>
__global__ void __launch_bounds__(256, 1)
gemm_mma(const bf16* __restrict__ Ahi, const bf16* __restrict__ Alo,
         const bf16* __restrict__ Whi, const bf16* __restrict__ Wlo,
         const float* __restrict__ bias,
         bf16* __restrict__ Ohi, bf16* __restrict__ Olo,
         float* __restrict__ Ofp, int ldc)
{
    constexpr int KPAD   = NC * 32;
    constexpr int WN     = NT / 2;          // warp n-extent (4m x 2n warps)
    constexpr int NB     = WN / 16;         // B ldmatrix.x4 count per split per k16
    constexpr int NF     = WN / 8;          // n8 mma frags per warp
    constexpr int ABYTES = 128 * 128;
    constexpr int BBYTES = NT * 128;
    constexpr int STAGE  = ABYTES + BBYTES;

    extern __shared__ __align__(1024) char sm[];
    const uint32_t sb = smem_u32(sm);

    const int tid  = threadIdx.x;
    const int wid  = tid >> 5;
    const int lane = tid & 31;
    const int m0   = blockIdx.y * 128;
    const int n0   = blockIdx.x * NT;
    const int wm   = (wid >> 1) * 32;
    const int wn   = (wid & 1) * WN;

    float acc[2][NF][4];
    #pragma unroll
    for (int i = 0; i < 2; i++)
        #pragma unroll
        for (int j = 0; j < NF; j++)
            #pragma unroll
            for (int q = 0; q < 4; q++) acc[i][j][q] = 0.0f;

    // ---- staging: chunk c -> stage buffer s ----
    auto stage = [&](int c, int s) {
        const uint32_t sA = sb + s * STAGE;
        const uint32_t sB = sA + ABYTES;
        #pragma unroll
        for (int i = tid; i < 1024; i += 256) {          // A: 128 rows x 8 granules
            int r = i >> 3, cc = i & 7;
            uint32_t d = sA + r * 128 + ((cc ^ (r & 7)) << 4);
            const bf16* src = (cc < 4)
                ? Ahi + (size_t)(m0 + r) * KPAD + c * 32 + cc * 8
                : Alo + (size_t)(m0 + r) * KPAD + c * 32 + (cc - 4) * 8;
            cpa16(d, src);
        }
        #pragma unroll
        for (int i = tid; i < NT * 8; i += 256) {        // B: NT rows x 8 granules
            int r = i >> 3, cc = i & 7;
            uint32_t d = sB + r * 128 + ((cc ^ (r & 7)) << 4);
            const bf16* src = (cc < 4)
                ? Whi + (size_t)(n0 + r) * KPAD + c * 32 + cc * 8
                : Wlo + (size_t)(n0 + r) * KPAD + c * 32 + (cc - 4) * 8;
            cpa16(d, src);
        }
        CP_COMMIT();
    };

    stage(0, 0);

    for (int c = 0; c < NC; ++c) {
        if (c + 1 < NC) { stage(c + 1, (c + 1) & 1); cp_wait<1>(); }
        else           { cp_wait<0>(); }
        __syncthreads();

        const uint32_t sA = sb + (c & 1) * STAGE;
        const uint32_t sB = sA + ABYTES;

        #pragma unroll
        for (int ks = 0; ks < 2; ++ks) {                 // two k16 steps per chunk
            uint32_t ah[2][4], al[2][4];
            #pragma unroll
            for (int mi = 0; mi < 2; ++mi) {
                int row = wm + mi * 16 + (lane & 15);
                int gh  = ks * 2 + (lane >> 4);          // hi granules 0-3
                LDM4(ah[mi], sA + row * 128 + ((gh ^ (row & 7)) << 4));
                int gl  = gh + 4;                        // lo granules 4-7
                LDM4(al[mi], sA + row * 128 + ((gl ^ (row & 7)) << 4));
            }
            uint32_t bh[NF][2], bl[NF][2];
            #pragma unroll
            for (int nb = 0; nb < NB; ++nb) {
                int row = wn + nb * 16 + (lane & 15);
                int gh  = ks * 2 + (lane >> 4);
                uint32_t t[4];
                LDM4(t, sB + row * 128 + ((gh ^ (row & 7)) << 4));
                bh[2*nb][0] = t[0]; bh[2*nb][1] = t[2];
                bh[2*nb+1][0] = t[1]; bh[2*nb+1][1] = t[3];
                int gl  = gh + 4;
                LDM4(t, sB + row * 128 + ((gl ^ (row & 7)) << 4));
                bl[2*nb][0] = t[0]; bl[2*nb][1] = t[2];
                bl[2*nb+1][0] = t[1]; bl[2*nb+1][1] = t[3];
            }
            #pragma unroll
            for (int mi = 0; mi < 2; ++mi)
                #pragma unroll
                for (int nf = 0; nf < NF; ++nf) {
                    MMA_BF16(acc[mi][nf], ah[mi], bh[nf]);
                    MMA_BF16(acc[mi][nf], al[mi], bh[nf]);
                    MMA_BF16(acc[mi][nf], ah[mi], bl[nf]);
                }
        }
        __syncthreads();
    }

    // ---- epilogue: bias + relu (+ split for next layer) ----
    #pragma unroll
    for (int mi = 0; mi < 2; ++mi) {
        #pragma unroll
        for (int nf = 0; nf < NF; ++nf) {
            int r0 = m0 + wm + mi * 16 + (lane >> 2);
            int cb = n0 + wn + nf * 8 + (lane & 3) * 2;
            float bia0 = bias[cb], bia1 = bias[cb + 1];
            #pragma unroll
            for (int half = 0; half < 2; ++half) {
                int r = r0 + half * 8;
                float v0 = fmaxf(acc[mi][nf][half * 2]     + bia0, 0.0f);
                float v1 = fmaxf(acc[mi][nf][half * 2 + 1] + bia1, 0.0f);
                if (SPLIT_OUT) {
                    bf16 h0 = __float2bfloat16(v0);
                    bf16 h1 = __float2bfloat16(v1);
                    __nv_bfloat162 hh; hh.x = h0; hh.y = h1;
                    __nv_bfloat162 ll;
                    ll.x = __float2bfloat16(v0 - __bfloat162float(h0));
                    ll.y = __float2bfloat16(v1 - __bfloat162float(h1));
                    *(__nv_bfloat162*)(Ohi + (size_t)r * ldc + cb) = hh;
                    *(__nv_bfloat162*)(Olo + (size_t)r * ldc + cb) = ll;
                } else {
                    float2 vv; vv.x = v0; vv.y = v1;
                    *(float2*)(Ofp + (size_t)r * ldc + cb) = vv;
                }
            }
        }
    }
}

// ---------------------------------------------------------------------------
// Prep kernels
// ---------------------------------------------------------------------------
__global__ void conv_x(const float* __restrict__ x, bf16* __restrict__ hi, bf16* __restrict__ lo) {
    size_t i = (size_t)blockIdx.x * blockDim.x + threadIdx.x;
    if (i >= (size_t)B_ROWS * 384) return;
    size_t row = i / 384; int col = (int)(i % 384);
    float v = (col < T_DIM) ? x[row * T_DIM + col] : 0.0f;
    bf16 h = __float2bfloat16(v);
    hi[i] = h;
    lo[i] = __float2bfloat16(v - __bfloat162float(h));
}

__global__ void conv_weight(const float* __restrict__ W, int K, int N, int Kpad,
                            bf16* __restrict__ hi, bf16* __restrict__ lo) {
    int i = blockIdx.x * blockDim.x + threadIdx.x;
    if (i >= N * Kpad) return;
    int n = i / Kpad, kp = i % Kpad;
    float v = (kp < K) ? W[(size_t)kp * N + n] : 0.0f;
    bf16 h = __float2bfloat16(v);
    hi[i] = h;
    lo[i] = __float2bfloat16(v - __bfloat162float(h));
}

// ---------------------------------------------------------------------------
// Per-row statistics + 6->32 projection -> comb cols [128,160); zero [160,192)
// ---------------------------------------------------------------------------
__global__ void stats_kernel(const float* __restrict__ x,
                             const float* __restrict__ Ws,
                             const float* __restrict__ bs,
                             bf16* __restrict__ cbhi, bf16* __restrict__ cblo)
{
    int gwarp = (blockIdx.x * blockDim.x + threadIdx.x) >> 5;
    int lane  = threadIdx.x & 31;
    if (gwarp >= B_ROWS) return;

    const float* row = x + (size_t)gwarp * T_DIM;
    constexpr int NV = (T_DIM + 31) / 32;
    float v[NV];
    float sum = 0.0f, mn = INFINITY, mx = -INFINITY;
    #pragma unroll
    for (int i = 0; i < NV; i++) {
        int k = lane + 32 * i;
        float t = (k < T_DIM) ? row[k] : 0.0f;
        v[i] = t;
        if (k < T_DIM) { sum += t; mn = fminf(mn, t); mx = fmaxf(mx, t); }
    }
    #pragma unroll
    for (int off = 16; off; off >>= 1) {
        sum += __shfl_xor_sync(0xffffffffu, sum, off);
        mn   = fminf(mn, __shfl_xor_sync(0xffffffffu, mn, off));
        mx   = fmaxf(mx, __shfl_xor_sync(0xffffffffu, mx, off));
    }
    float mean = sum / (float)T_DIM;
    float s2 = 0.0f, s3 = 0.0f, s4 = 0.0f;
    #pragma unroll
    for (int i = 0; i < NV; i++) {
        int k = lane + 32 * i;
        if (k < T_DIM) {
            float c  = v[i] - mean;
            float c2 = c * c;
            s2 += c2; s3 += c2 * c; s4 += c2 * c2;
        }
    }
    #pragma unroll
    for (int off = 16; off; off >>= 1) {
        s2 += __shfl_xor_sync(0xffffffffu, s2, off);
        s3 += __shfl_xor_sync(0xffffffffu, s3, off);
        s4 += __shfl_xor_sync(0xffffffffu, s4, off);
    }
    float var  = s2 / (float)(T_DIM - 1);
    float sd   = sqrtf(var);
    float skew = (s3 / (float)T_DIM) / (sd * sd * sd + 1e-8f);
    float kurt = (s4 / (float)T_DIM) / (var * var + 1e-8f);

    float st[6] = { mean, sd, mn, mx, skew, kurt };
    float o = bs[lane];
    #pragma unroll
    for (int i = 0; i < 6; i++) o = fmaf(st[i], Ws[i * 32 + lane], o);

    bf16 h = __float2bfloat16(o);
    size_t base = (size_t)gwarp * 192;
    cbhi[base + 128 + lane] = h;
    cblo[base + 128 + lane] = __float2bfloat16(o - __bfloat162float(h));
    bf16 z = __float2bfloat16(0.0f);
    cbhi[base + 160 + lane] = z;
    cblo[base + 160 + lane] = z;
}

// ---------------------------------------------------------------------------
// Final head: out = sigmoid(c2 @ Wc3 + bc3) * 4 + 6
// ---------------------------------------------------------------------------
__global__ void head_final(const float* __restrict__ c2,
                           const float* __restrict__ Wc3,
                           const float* __restrict__ bc3,
                           float* __restrict__ out)
{
    int gwarp = (blockIdx.x * blockDim.x + threadIdx.x) >> 5;
    int lane  = threadIdx.x & 31;
    if (gwarp >= B_ROWS) return;
    float v = c2[(size_t)gwarp * 32 + lane] * Wc3[lane];
    #pragma unroll
    for (int off = 16; off; off >>= 1) v += __shfl_xor_sync(0xffffffffu, v, off);
    if (lane == 0) {
        float z = v + bc3[0];
        out[gwarp] = 4.0f / (1.0f + expf(-z)) + 6.0f;
    }
}

// ---------------------------------------------------------------------------
// Launch
// ---------------------------------------------------------------------------
extern "C" void kernel_launch(void* const* d_in, const int* in_sizes, int n_in,
                              void* d_out, int out_size)
{
    const float* x   = (const float*)d_in[0];
    const float* W1  = (const float*)d_in[1];
    const float* b1  = (const float*)d_in[2];
    const float* W2  = (const float*)d_in[3];
    const float* b2  = (const float*)d_in[4];
    const float* W3  = (const float*)d_in[5];
    const float* b3  = (const float*)d_in[6];
    const float* Ws  = (const float*)d_in[7];
    const float* bs  = (const float*)d_in[8];
    const float* Wc1 = (const float*)d_in[9];
    const float* bc1 = (const float*)d_in[10];
    const float* Wc2 = (const float*)d_in[11];
    const float* bc2 = (const float*)d_in[12];
    const float* Wc3 = (const float*)d_in[13];
    const float* bc3 = (const float*)d_in[14];
    float* out = (float*)d_out;

    bf16 *xhi, *xlo, *h1hi, *h1lo, *h2hi, *h2lo, *cbhi, *cblo, *c1hi, *c1lo;
    bf16 *w1hi, *w1lo, *w2hi, *w2lo, *w3hi, *w3lo, *w4hi, *w4lo, *w5hi, *w5lo;
    float* c2;
    cudaGetSymbolAddress((void**)&xhi,  g_xhi);  cudaGetSymbolAddress((void**)&xlo,  g_xlo);
    cudaGetSymbolAddress((void**)&h1hi, g_h1hi); cudaGetSymbolAddress((void**)&h1lo, g_h1lo);
    cudaGetSymbolAddress((void**)&h2hi, g_h2hi); cudaGetSymbolAddress((void**)&h2lo, g_h2lo);
    cudaGetSymbolAddress((void**)&cbhi, g_cbhi); cudaGetSymbolAddress((void**)&cblo, g_cblo);
    cudaGetSymbolAddress((void**)&c1hi, g_c1hi); cudaGetSymbolAddress((void**)&c1lo, g_c1lo);
    cudaGetSymbolAddress((void**)&c2,   g_c2);
    cudaGetSymbolAddress((void**)&w1hi, g_w1hi); cudaGetSymbolAddress((void**)&w1lo, g_w1lo);
    cudaGetSymbolAddress((void**)&w2hi, g_w2hi); cudaGetSymbolAddress((void**)&w2lo, g_w2lo);
    cudaGetSymbolAddress((void**)&w3hi, g_w3hi); cudaGetSymbolAddress((void**)&w3lo, g_w3lo);
    cudaGetSymbolAddress((void**)&w4hi, g_w4hi); cudaGetSymbolAddress((void**)&w4lo, g_w4lo);
    cudaGetSymbolAddress((void**)&w5hi, g_w5hi); cudaGetSymbolAddress((void**)&w5lo, g_w5lo);

    // 2 stages x (A 16KB + B NT*128B)
    const int SM128 = 2 * (16384 + 128 * 128);  // 65536
    const int SM64  = 2 * (16384 + 64  * 128);  // 49152
    const int SM32  = 2 * (16384 + 32  * 128);  // 40960
    cudaFuncSetAttribute(gemm_mma<128, 12, true>, cudaFuncAttributeMaxDynamicSharedMemorySize, SM128);
    cudaFuncSetAttribute(gemm_mma<128, 16, true>, cudaFuncAttributeMaxDynamicSharedMemorySize, SM128);
    cudaFuncSetAttribute(gemm_mma<128, 8,  true>, cudaFuncAttributeMaxDynamicSharedMemorySize, SM128);
    cudaFuncSetAttribute(gemm_mma<64,  6,  true>, cudaFuncAttributeMaxDynamicSharedMemorySize, SM64);
    cudaFuncSetAttribute(gemm_mma<32,  2, false>, cudaFuncAttributeMaxDynamicSharedMemorySize, SM32);

    // Prep: split-precision conversions
    conv_x<<<(B_ROWS * 384 + 255) / 256, 256>>>(x, xhi, xlo);
    conv_weight<<<(512 * 384 + 255) / 256, 256>>>(W1, 365, 512, 384, w1hi, w1lo);
    conv_weight<<<(256 * 512 + 255) / 256, 256>>>(W2, 512, 256, 512, w2hi, w2lo);
    conv_weight<<<(128 * 256 + 255) / 256, 256>>>(W3, 256, 128, 256, w3hi, w3lo);
    conv_weight<<<(64 * 192 + 255) / 256, 256>>>(Wc1, 160, 64, 192, w4hi, w4lo);
    conv_weight<<<(32 * 64 + 255) / 256, 256>>>(Wc2, 64, 32, 64, w5hi, w5lo);

    // Stats (independent; must precede L4)
    stats_kernel<<<B_ROWS / 8, 256>>>(x, Ws, bs, cbhi, cblo);

    // GEMM chain (mma.sync HMMA, split-bf16)
    gemm_mma<128, 12, true><<<dim3(4, B_ROWS / 128), 256, SM128>>>(
        xhi, xlo, w1hi, w1lo, b1, h1hi, h1lo, nullptr, 512);
    gemm_mma<128, 16, true><<<dim3(2, B_ROWS / 128), 256, SM128>>>(
        h1hi, h1lo, w2hi, w2lo, b2, h2hi, h2lo, nullptr, 256);
    gemm_mma<128, 8, true><<<dim3(1, B_ROWS / 128), 256, SM128>>>(
        h2hi, h2lo, w3hi, w3lo, b3, cbhi, cblo, nullptr, 192);
    gemm_mma<64, 6, true><<<dim3(1, B_ROWS / 128), 256, SM64>>>(
        cbhi, cblo, w4hi, w4lo, bc1, c1hi, c1lo, nullptr, 64);
    gemm_mma<32, 2, false><<<dim3(1, B_ROWS / 128), 256, SM32>>>(
        c1hi, c1lo, w5hi, w5lo, bc2, nullptr, nullptr, c2, 32);

    head_final<<<B_ROWS / 8, 256>>>(c2, Wc3, bc3, out);
}

// round 4
// speedup vs baseline: 7.3969x; 3.0129x over previous
#include <cuda_runtime.h>
#include <cuda_fp16.h>
#include <math.h>
#include <stdint.h>

#define B_ROWS 65536
#define T_DIM  365

// ---------------------------------------------------------------------------
// Scratch (device globals)
// ---------------------------------------------------------------------------
__device__ half g_x  [(size_t)B_ROWS * 384];
__device__ half g_h1 [(size_t)B_ROWS * 512];
__device__ half g_h2 [(size_t)B_ROWS * 256];
__device__ half g_cb [(size_t)B_ROWS * 192];   // [h3(128) | stats(32) | zero(32)]
__device__ half g_c1 [(size_t)B_ROWS * 64];
__device__ float g_c2[(size_t)B_ROWS * 32];
// weights transposed to [N, Kpad] fp16
__device__ half g_w1[512*384];
__device__ half g_w2[256*512];
__device__ half g_w3[128*256];
__device__ half g_w4[64*192];
__device__ half g_w5[32*64];

// ---------------------------------------------------------------------------
// Baseline-PTX helpers (sm_80+; assemble on plain sm_103)
// ---------------------------------------------------------------------------
__device__ __forceinline__ uint32_t smem_u32(const void* p) {
    uint32_t a;
    asm("{ .reg .u64 t; cvta.to.shared.u64 t, %1; cvt.u32.u64 %0, t; }" : "=r"(a) : "l"(p));
    return a;
}
__device__ __forceinline__ void cpa16(uint32_t dst, const void* src) {
    asm volatile("cp.async.cg.shared.global [%0], [%1], 16;" :: "r"(dst), "l"(src));
}
#define CP_COMMIT() asm volatile("cp.async.commit_group;" ::: "memory")
template<int N>
__device__ __forceinline__ void cp_wait() {
    asm volatile("cp.async.wait_group %0;" :: "n"(N) : "memory");
}
#define LDM4(r, addr) \
    asm volatile("ldmatrix.sync.aligned.m8n8.x4.shared.b16 {%0,%1,%2,%3}, [%4];" \
        : "=r"((r)[0]), "=r"((r)[1]), "=r"((r)[2]), "=r"((r)[3]) : "r"(addr))
#define MMA_F16(d, a, b) \
    asm volatile("mma.sync.aligned.m16n8k16.row.col.f32.f16.f16.f32 " \
        "{%0,%1,%2,%3}, {%4,%5,%6,%7}, {%8,%9}, {%0,%1,%2,%3};" \
        : "+f"((d)[0]), "+f"((d)[1]), "+f"((d)[2]), "+f"((d)[3]) \
        : "r"((a)[0]), "r"((a)[1]), "r"((a)[2]), "r"((a)[3]), \
          "r"((b)[0]), "r"((b)[1]))

// ---------------------------------------------------------------------------
// fp16 mma.sync GEMM: out[128 x NT] = relu(A @ W^T + bias)
// A: [B, KPAD] fp16; W: [N, KPAD] fp16 (pre-transposed). fp32 reg accum.
// k-chunk 64 (128B rows, 8x16B granules, XOR-(r&7) swizzle).
// 3-stage cp.async pipeline; 8 warps = 4m x 2n.
// ---------------------------------------------------------------------------
template<int NT, int NC, bool FP32_OUT>
__global__ void __launch_bounds__(256, 2)
gemm_mma(const half* __restrict__ A, const half* __restrict__ W,
         const float* __restrict__ bias,
         half* __restrict__ Oh, float* __restrict__ Of, int ldc)
{
    constexpr int KPAD   = NC * 64;
    constexpr int WN     = NT / 2;          // warp n-extent
    constexpr int NB     = WN / 16;         // B ldmatrix.x4 per k16
    constexpr int NF     = WN / 8;          // n8 frags per warp
    constexpr int ABYTES = 128 * 128;
    constexpr int BBYTES = NT * 128;
    constexpr int STAGE  = ABYTES + BBYTES;

    extern __shared__ __align__(1024) char sm[];
    const uint32_t sb = smem_u32(sm);

    const int tid  = threadIdx.x;
    const int wid  = tid >> 5;
    const int lane = tid & 31;
    const int m0   = blockIdx.y * 128;
    const int n0   = blockIdx.x * NT;
    const int wm   = (wid >> 1) * 32;
    const int wn   = (wid & 1) * WN;

    float acc[2][NF][4];
    #pragma unroll
    for (int i = 0; i < 2; i++)
        #pragma unroll
        for (int j = 0; j < NF; j++)
            #pragma unroll
            for (int q = 0; q < 4; q++) acc[i][j][q] = 0.0f;

    auto stage = [&](int c) {
        const uint32_t sA = sb + (c % 3) * STAGE;
        const uint32_t sB = sA + ABYTES;
        #pragma unroll
        for (int i = tid; i < 1024; i += 256) {          // A: 128 rows x 8 granules
            int r = i >> 3, cc = i & 7;
            cpa16(sA + r * 128 + ((cc ^ (r & 7)) << 4),
                  A + (size_t)(m0 + r) * KPAD + c * 64 + cc * 8);
        }
        #pragma unroll
        for (int i = tid; i < NT * 8; i += 256) {        // B: NT rows x 8 granules
            int r = i >> 3, cc = i & 7;
            cpa16(sB + r * 128 + ((cc ^ (r & 7)) << 4),
                  W + (size_t)(n0 + r) * KPAD + c * 64 + cc * 8);
        }
        CP_COMMIT();
    };

    stage(0);
    if (NC > 1) stage(1);

    for (int c = 0; c < NC; ++c) {
        if (c + 2 < NC)      { stage(c + 2); cp_wait<2>(); }
        else if (c + 1 < NC) { cp_wait<1>(); }
        else                 { cp_wait<0>(); }
        __syncthreads();

        const uint32_t sA = sb + (c % 3) * STAGE;
        const uint32_t sB = sA + ABYTES;

        #pragma unroll
        for (int ks = 0; ks < 4; ++ks) {                 // four k16 steps per chunk
            uint32_t a[2][4];
            #pragma unroll
            for (int mi = 0; mi < 2; ++mi) {
                int row = wm + mi * 16 + (lane & 15);
                int g   = ks * 2 + (lane >> 4);
                LDM4(a[mi], sA + row * 128 + ((g ^ (row & 7)) << 4));
            }
            uint32_t b[NF][2];
            #pragma unroll
            for (int nb = 0; nb < NB; ++nb) {
                int row = wn + nb * 16 + (lane & 15);
                int g   = ks * 2 + (lane >> 4);
                uint32_t t[4];
                LDM4(t, sB + row * 128 + ((g ^ (row & 7)) << 4));
                b[2*nb][0]   = t[0]; b[2*nb][1]   = t[2];
                b[2*nb+1][0] = t[1]; b[2*nb+1][1] = t[3];
            }
            #pragma unroll
            for (int mi = 0; mi < 2; ++mi)
                #pragma unroll
                for (int nf = 0; nf < NF; ++nf)
                    MMA_F16(acc[mi][nf], a[mi], b[nf]);
        }
        __syncthreads();
    }

    // ---- epilogue: bias + relu, store fp16 (or fp32 for last layer) ----
    #pragma unroll
    for (int mi = 0; mi < 2; ++mi) {
        #pragma unroll
        for (int nf = 0; nf < NF; ++nf) {
            int r0 = m0 + wm + mi * 16 + (lane >> 2);
            int cb = n0 + wn + nf * 8 + (lane & 3) * 2;
            float bia0 = bias[cb], bia1 = bias[cb + 1];
            #pragma unroll
            for (int h = 0; h < 2; ++h) {
                int r = r0 + h * 8;
                float v0 = fmaxf(acc[mi][nf][h * 2]     + bia0, 0.0f);
                float v1 = fmaxf(acc[mi][nf][h * 2 + 1] + bia1, 0.0f);
                if (FP32_OUT) {
                    float2 vv; vv.x = v0; vv.y = v1;
                    *(float2*)(Of + (size_t)r * ldc + cb) = vv;
                } else {
                    *(__half2*)(Oh + (size_t)r * ldc + cb) = __floats2half2_rn(v0, v1);
                }
            }
        }
    }
}

// ---------------------------------------------------------------------------
// Fused: x -> fp16 (padded to 384) + per-row stats + 6->32 projection.
// One warp per row, single global pass.
// ---------------------------------------------------------------------------
__global__ void conv_stats(const float* __restrict__ x,
                           const float* __restrict__ Ws,
                           const float* __restrict__ bs,
                           half* __restrict__ xh, half* __restrict__ cb)
{
    int gwarp = (blockIdx.x * blockDim.x + threadIdx.x) >> 5;
    int lane  = threadIdx.x & 31;
    if (gwarp >= B_ROWS) return;

    const float* row = x + (size_t)gwarp * T_DIM;
    constexpr int NV = 12;                   // ceil(384/32)
    float v[NV];
    float sum = 0.0f, mn = INFINITY, mx = -INFINITY;
    #pragma unroll
    for (int i = 0; i < NV; i++) {
        int k = lane + 32 * i;
        float t = (k < T_DIM) ? row[k] : 0.0f;
        v[i] = t;
        if (k < T_DIM) { sum += t; mn = fminf(mn, t); mx = fmaxf(mx, t); }
    }
    // write fp16 x (zero-padded)
    half* xr = xh + (size_t)gwarp * 384;
    #pragma unroll
    for (int i = 0; i < NV; i++) xr[lane + 32 * i] = __float2half_rn(v[i]);

    #pragma unroll
    for (int off = 16; off; off >>= 1) {
        sum += __shfl_xor_sync(0xffffffffu, sum, off);
        mn   = fminf(mn, __shfl_xor_sync(0xffffffffu, mn, off));
        mx   = fmaxf(mx, __shfl_xor_sync(0xffffffffu, mx, off));
    }
    float mean = sum / (float)T_DIM;
    float s2 = 0.0f, s3 = 0.0f, s4 = 0.0f;
    #pragma unroll
    for (int i = 0; i < NV; i++) {
        int k = lane + 32 * i;
        if (k < T_DIM) {
            float c  = v[i] - mean;
            float c2 = c * c;
            s2 += c2; s3 += c2 * c; s4 += c2 * c2;
        }
    }
    #pragma unroll
    for (int off = 16; off; off >>= 1) {
        s2 += __shfl_xor_sync(0xffffffffu, s2, off);
        s3 += __shfl_xor_sync(0xffffffffu, s3, off);
        s4 += __shfl_xor_sync(0xffffffffu, s4, off);
    }
    float var  = s2 / (float)(T_DIM - 1);
    float sd   = sqrtf(var);
    float skew = (s3 / (float)T_DIM) / (sd * sd * sd + 1e-8f);
    float kurt = (s4 / (float)T_DIM) / (var * var + 1e-8f);

    float st[6] = { mean, sd, mn, mx, skew, kurt };
    float o = bs[lane];
    #pragma unroll
    for (int i = 0; i < 6; i++) o = fmaf(st[i], Ws[i * 32 + lane], o);

    size_t base = (size_t)gwarp * 192;
    cb[base + 128 + lane] = __float2half_rn(o);
    cb[base + 160 + lane] = __float2half_rn(0.0f);
}

// W [K,N] fp32 -> Wt [N,Kpad] fp16 (transposed + zero-padded)
__global__ void conv_weight(const float* __restrict__ W, int K, int N, int Kpad,
                            half* __restrict__ o) {
    int i = blockIdx.x * blockDim.x + threadIdx.x;
    if (i >= N * Kpad) return;
    int n = i / Kpad, kp = i % Kpad;
    o[i] = __float2half_rn((kp < K) ? W[(size_t)kp * N + n] : 0.0f);
}

// ---------------------------------------------------------------------------
// Final head: out = sigmoid(c2 @ Wc3 + bc3) * 4 + 6
// ---------------------------------------------------------------------------
__global__ void head_final(const float* __restrict__ c2,
                           const float* __restrict__ Wc3,
                           const float* __restrict__ bc3,
                           float* __restrict__ out)
{
    int gwarp = (blockIdx.x * blockDim.x + threadIdx.x) >> 5;
    int lane  = threadIdx.x & 31;
    if (gwarp >= B_ROWS) return;
    float v = c2[(size_t)gwarp * 32 + lane] * Wc3[lane];
    #pragma unroll
    for (int off = 16; off; off >>= 1) v += __shfl_xor_sync(0xffffffffu, v, off);
    if (lane == 0) {
        float z = v + bc3[0];
        out[gwarp] = 4.0f / (1.0f + expf(-z)) + 6.0f;
    }
}

// ---------------------------------------------------------------------------
// Launch  (order arranged so ncu -s 5 lands on gemm1)
// ---------------------------------------------------------------------------
extern "C" void kernel_launch(void* const* d_in, const int* in_sizes, int n_in,
                              void* d_out, int out_size)
{
    const float* x   = (const float*)d_in[0];
    const float* W1  = (const float*)d_in[1];
    const float* b1  = (const float*)d_in[2];
    const float* W2  = (const float*)d_in[3];
    const float* b2  = (const float*)d_in[4];
    const float* W3  = (const float*)d_in[5];
    const float* b3  = (const float*)d_in[6];
    const float* Ws  = (const float*)d_in[7];
    const float* bs  = (const float*)d_in[8];
    const float* Wc1 = (const float*)d_in[9];
    const float* bc1 = (const float*)d_in[10];
    const float* Wc2 = (const float*)d_in[11];
    const float* bc2 = (const float*)d_in[12];
    const float* Wc3 = (const float*)d_in[13];
    const float* bc3 = (const float*)d_in[14];
    float* out = (float*)d_out;

    half *xh, *h1, *h2, *cb, *c1, *w1, *w2, *w3, *w4, *w5;
    float* c2;
    cudaGetSymbolAddress((void**)&xh, g_x);
    cudaGetSymbolAddress((void**)&h1, g_h1);
    cudaGetSymbolAddress((void**)&h2, g_h2);
    cudaGetSymbolAddress((void**)&cb, g_cb);
    cudaGetSymbolAddress((void**)&c1, g_c1);
    cudaGetSymbolAddress((void**)&c2, g_c2);
    cudaGetSymbolAddress((void**)&w1, g_w1);
    cudaGetSymbolAddress((void**)&w2, g_w2);
    cudaGetSymbolAddress((void**)&w3, g_w3);
    cudaGetSymbolAddress((void**)&w4, g_w4);
    cudaGetSymbolAddress((void**)&w5, g_w5);

    // 3 stages x (A 16KB + B NT*128B)
    const int SM128 = 3 * (16384 + 128 * 128);  // 98304
    const int SM64  = 3 * (16384 + 64  * 128);  // 73728
    const int SM32  = 3 * (16384 + 32  * 128);  // 61440
    cudaFuncSetAttribute(gemm_mma<128, 6, false>, cudaFuncAttributeMaxDynamicSharedMemorySize, SM128);
    cudaFuncSetAttribute(gemm_mma<128, 8, false>, cudaFuncAttributeMaxDynamicSharedMemorySize, SM128);
    cudaFuncSetAttribute(gemm_mma<128, 4, false>, cudaFuncAttributeMaxDynamicSharedMemorySize, SM128);
    cudaFuncSetAttribute(gemm_mma<64,  3, false>, cudaFuncAttributeMaxDynamicSharedMemorySize, SM64);
    cudaFuncSetAttribute(gemm_mma<32,  1, true >, cudaFuncAttributeMaxDynamicSharedMemorySize, SM32);

    // #0: fused x-conversion + stats
    conv_stats<<<B_ROWS / 8, 256>>>(x, Ws, bs, xh, cb);
    // #1-#4: weight conversions
    conv_weight<<<(512 * 384 + 255) / 256, 256>>>(W1, 365, 512, 384, w1);
    conv_weight<<<(256 * 512 + 255) / 256, 256>>>(W2, 512, 256, 512, w2);
    conv_weight<<<(128 * 256 + 255) / 256, 256>>>(W3, 256, 128, 256, w3);
    conv_weight<<<(64 * 192 + 255) / 256, 256>>>(Wc1, 160, 64, 192, w4);

    // #5: gemm1 (profiled by ncu -s 5)
    gemm_mma<128, 6, false><<<dim3(4, B_ROWS / 128), 256, SM128>>>(
        xh, w1, b1, h1, nullptr, 512);
    // #6-#7
    gemm_mma<128, 8, false><<<dim3(2, B_ROWS / 128), 256, SM128>>>(
        h1, w2, b2, h2, nullptr, 256);
    gemm_mma<128, 4, false><<<dim3(1, B_ROWS / 128), 256, SM128>>>(
        h2, w3, b3, cb, nullptr, 192);
    // #8: last weight conversion
    conv_weight<<<(32 * 64 + 255) / 256, 256>>>(Wc2, 64, 32, 64, w5);
    // #9-#10
    gemm_mma<64, 3, false><<<dim3(1, B_ROWS / 128), 256, SM64>>>(
        cb, w4, bc1, c1, nullptr, 64);
    gemm_mma<32, 1, true><<<dim3(1, B_ROWS / 128), 256, SM32>>>(
        c1, w5, bc2, nullptr, c2, 32);
    // #11
    head_final<<<B_ROWS / 8, 256>>>(c2, Wc3, bc3, out);
}